// round 7
// baseline (speedup 1.0000x reference)
#include <cuda_runtime.h>
#include <cuda_fp16.h>
#include <math.h>

typedef unsigned int u32;

#define NSTEPS 511
#define Tt     512
#define NTHR   256
#define MROWS  128

// ---- smem byte offsets ----
#define SM_W1 0            // 16 tiles * 512B
#define SM_W2 8192         // 32 tiles
#define SM_W3 24576        // 48 tiles
#define SM_B1 49152        // f32[64]
#define SM_B2 49408        // f32[64]
#define SM_B3 49664        // f32[96] (permuted)
#define SM_KST 50048       // f32[6][16][NTHR]
#define SMEM_BYTES (SM_KST + 6*16*NTHR*4)   // 148,352 B

__constant__ float cA6[6][5] = {
    {0.f,0.f,0.f,0.f,0.f},
    {0.161f,0.f,0.f,0.f,0.f},
    {-0.008480655492356989f,0.335480655492357f,0.f,0.f,0.f},
    {2.8971530571054935f,-6.359448489975075f,4.3622954328695815f,0.f,0.f},
    {5.325864828439257f,-11.748883564062828f,7.4955393428898365f,-0.09249506636175525f,0.f},
    {5.86145544294642f,-12.92096931784711f,8.159367898576159f,-0.071584973281401f,-0.028269050394068383f}};
__constant__ float cBt[6] = {
    0.09646076681806523f,0.01f,0.4798896504144996f,
    1.379008574103742f,-3.290069515436081f,2.324710524099774f};

// physical A-col p (0..31) -> logical h index
__device__ __forceinline__ int hphys(int p){
    return 8*((p&7)>>1) + 2*(p>>3) + (p&1);
}
// physical L3 out col p3 (0..95) -> logical w3 row (3h+c)
__device__ __forceinline__ int w3row(int p3){
    int j = p3>>3, r = p3&7, tg = r>>1, e = r&1;
    int q = 2*j + e, d = q/3, c = q%3;
    return 3*(8*tg + d) + c;
}

__device__ __forceinline__ u32 h2p(float x, float y){
    return (u32)__half_as_ushort(__float2half_rn(x))
         | ((u32)__half_as_ushort(__float2half_rn(y)) << 16);
}
__device__ __forceinline__ void split2(float x, float y, u32& hi, u32& lo){
    __half hx = __float2half_rn(x), hy = __float2half_rn(y);
    hi = (u32)__half_as_ushort(hx) | ((u32)__half_as_ushort(hy) << 16);
    lo = h2p(x - __half2float(hx), y - __half2float(hy));
}

__device__ __forceinline__ void mma16816(float* c, const u32* a, u32 b0, u32 b1){
    asm("mma.sync.aligned.m16n8k16.row.col.f32.f16.f16.f32 "
        "{%0,%1,%2,%3}, {%4,%5,%6,%7}, {%8,%9}, {%0,%1,%2,%3};"
        : "+f"(c[0]), "+f"(c[1]), "+f"(c[2]), "+f"(c[3])
        : "r"(a[0]), "r"(a[1]), "r"(a[2]), "r"(a[3]), "r"(b0), "r"(b1));
}

// k-tile-outer / n-tile-inner: NJ-deep independent accumulator chains.
template<int NJ, int NT>
__device__ __forceinline__ void runLayer(const u32* __restrict__ tiles,
                                         const float* __restrict__ bias,
                                         const u32 (*ah)[4], const u32 (*al)[4],
                                         float (*C)[4], int lane, int tg)
{
    #pragma unroll
    for (int j=0;j<NJ;++j){
        float2 bb = *(const float2*)(bias + 8*j + 2*tg);
        C[j][0]=bb.x; C[j][1]=bb.y; C[j][2]=bb.x; C[j][3]=bb.y;
    }
    #pragma unroll
    for (int t=0;t<NT;++t){
        uint4 w[NJ];
        #pragma unroll
        for (int j=0;j<NJ;++j)
            w[j] = *(const uint4*)(tiles + (j*NT+t)*128 + lane*4);
        #pragma unroll
        for (int j=0;j<NJ;++j) mma16816(C[j], ah[t], w[j].x, w[j].y);  // Ah*Bh
        #pragma unroll
        for (int j=0;j<NJ;++j) mma16816(C[j], al[t], w[j].x, w[j].y);  // Al*Bh
        #pragma unroll
        for (int j=0;j<NJ;++j) mma16816(C[j], ah[t], w[j].z, w[j].w);  // Ah*Bl
    }
}

// tanh + hi/lo split: C n-tile pair (2t,2t+1) -> A k-tile t
template<int NTo>
__device__ __forceinline__ void actSplit(const float (*C)[4], u32 (*ah)[4], u32 (*al)[4]){
    #pragma unroll
    for (int t=0;t<NTo;++t){
        split2(tanhf(C[2*t][0]),   tanhf(C[2*t][1]),   ah[t][0], al[t][0]);
        split2(tanhf(C[2*t][2]),   tanhf(C[2*t][3]),   ah[t][1], al[t][1]);
        split2(tanhf(C[2*t+1][0]), tanhf(C[2*t+1][1]), ah[t][2], al[t][2]);
        split2(tanhf(C[2*t+1][2]), tanhf(C[2*t+1][3]), ah[t][3], al[t][3]);
    }
}

__global__ void __launch_bounds__(NTHR, 1)
ncde_mma(const float* __restrict__ times, const float* __restrict__ grad,
         const float* __restrict__ w1, const float* __restrict__ pb1,
         const float* __restrict__ w2, const float* __restrict__ pb2,
         const float* __restrict__ w3, const float* __restrict__ pb3,
         const float* __restrict__ w_enc, const float* __restrict__ b_enc,
         const float* __restrict__ w_ro, const float* __restrict__ b_ro,
         float* __restrict__ out, int Bn)
{
    extern __shared__ float sm[];
    char* smc = (char*)sm;
    u32* tw1 = (u32*)(smc + SM_W1);
    u32* tw2 = (u32*)(smc + SM_W2);
    u32* tw3 = (u32*)(smc + SM_W3);
    float* b1s = (float*)(smc + SM_B1);
    float* b2s = (float*)(smc + SM_B2);
    float* b3s = (float*)(smc + SM_B3);
    float* kbuf = (float*)(smc + SM_KST);

    const int tid = threadIdx.x, warp = tid>>5, lane = tid&31;
    const int g = lane>>2, tg = lane&3;

    // ---- build weight fragment tiles (hi/lo f16) ----
    for (int s = tid; s < 16*32; s += NTHR){
        int tile = s>>5, l = s&31;
        int j = tile>>1, t = tile&1;
        int gg = l>>2, tt = l&3;
        int n = 8*j+gg, k0 = 16*t+2*tt;
        float f0 = w1[n*32 + hphys(k0)],   f1 = w1[n*32 + hphys(k0+1)];
        float f8 = w1[n*32 + hphys(k0+8)], f9 = w1[n*32 + hphys(k0+9)];
        u32 h01,l01,h89,l89;
        split2(f0,f1,h01,l01); split2(f8,f9,h89,l89);
        u32* d = tw1 + tile*128 + l*4;
        d[0]=h01; d[1]=h89; d[2]=l01; d[3]=l89;
    }
    for (int s = tid; s < 32*32; s += NTHR){
        int tile = s>>5, l = s&31;
        int j = tile>>2, t = tile&3;
        int gg = l>>2, tt = l&3;
        int n = 8*j+gg, k0 = 16*t+2*tt;
        float f0 = w2[n*64+k0],   f1 = w2[n*64+k0+1];
        float f8 = w2[n*64+k0+8], f9 = w2[n*64+k0+9];
        u32 h01,l01,h89,l89;
        split2(f0,f1,h01,l01); split2(f8,f9,h89,l89);
        u32* d = tw2 + tile*128 + l*4;
        d[0]=h01; d[1]=h89; d[2]=l01; d[3]=l89;
    }
    for (int s = tid; s < 48*32; s += NTHR){
        int tile = s>>5, l = s&31;
        int j = tile>>2, t = tile&3;
        int gg = l>>2, tt = l&3;
        int n = 8*j+gg, k0 = 16*t+2*tt;
        int rr = w3row(n);
        float f0 = w3[rr*64+k0],   f1 = w3[rr*64+k0+1];
        float f8 = w3[rr*64+k0+8], f9 = w3[rr*64+k0+9];
        u32 h01,l01,h89,l89;
        split2(f0,f1,h01,l01); split2(f8,f9,h89,l89);
        u32* d = tw3 + tile*128 + l*4;
        d[0]=h01; d[1]=h89; d[2]=l01; d[3]=l89;
    }
    if (tid < 64) b1s[tid] = pb1[tid];
    if (tid < 64) b2s[tid] = pb2[tid];
    if (tid < 96) b3s[tid] = pb3[w3row(tid)];
    __syncthreads();

    // ---- per-thread state: rows g and g+8 of warp's 16-row block ----
    const int base = blockIdx.x*MROWS + warp*16;
    const int rowg = base + g, rowh = rowg + 8;
    const int rgc = (rowg < Bn) ? rowg : (Bn-1);
    const int rhc = (rowh < Bn) ? rowh : (Bn-1);
    const float dt = times[1] - times[0];
    const float* gA = grad + (size_t)rgc * (Tt*3);
    const float* gB = grad + (size_t)rhc * (Tt*3);

    float zg[8], zh[8];
    #pragma unroll
    for (int d=0; d<8; ++d){
        float v = w_enc[8*tg+d] + b_enc[8*tg+d];
        zg[d] = v; zh[d] = v;
    }

    #pragma unroll 1
    for (int n=0; n<NSTEPS; ++n){
        float dqg[3], dqh[3];
        #pragma unroll
        for (int c=0;c<3;++c){ dqg[c] = gA[n*3+c]*dt; dqh[c] = gB[n*3+c]*dt; }

        #pragma unroll 1
        for (int sg=0; sg<6; ++sg){
            // ---- stage combine: Y = z + sum_p A[sg][p] k_p ----
            float Yg[8], Yh[8];
            #pragma unroll
            for (int d=0;d<8;++d){ Yg[d]=zg[d]; Yh[d]=zh[d]; }
            for (int p=0;p<sg;++p){
                const float c = cA6[sg][p];
                #pragma unroll
                for (int d=0;d<8;++d){
                    Yg[d] = fmaf(c, kbuf[(p*16+d)*NTHR+tid],   Yg[d]);
                    Yh[d] = fmaf(c, kbuf[(p*16+8+d)*NTHR+tid], Yh[d]);
                }
            }
            u32 yah[2][4], yal[2][4];
            #pragma unroll
            for (int t=0;t<2;++t){
                split2(Yg[4*t],   Yg[4*t+1], yah[t][0], yal[t][0]);
                split2(Yh[4*t],   Yh[4*t+1], yah[t][1], yal[t][1]);
                split2(Yg[4*t+2], Yg[4*t+3], yah[t][2], yal[t][2]);
                split2(Yh[4*t+2], Yh[4*t+3], yah[t][3], yal[t][3]);
            }

            // ---- L1 ----
            float C1[8][4];
            runLayer<8,2>(tw1, b1s, yah, yal, C1, lane, tg);
            u32 a2h[4][4], a2l[4][4];
            actSplit<4>(C1, a2h, a2l);

            // ---- L2 ----
            float C2[8][4];
            runLayer<8,4>(tw2, b2s, a2h, a2l, C2, lane, tg);
            u32 a3h[4][4], a3l[4][4];
            actSplit<4>(C2, a3h, a3l);

            // ---- L3 ----
            float C3[12][4];
            runLayer<12,4>(tw3, b3s, a3h, a3l, C3, lane, tg);

            // ---- dq contraction -> k ----
            float nkg[8], nkh[8];
            #pragma unroll
            for (int d=0;d<8;++d){ nkg[d]=0.f; nkh[d]=0.f; }
            #pragma unroll
            for (int j=0;j<12;++j){
                #pragma unroll
                for (int e=0;e<2;++e){
                    const int q = 2*j+e, d = q/3, c = q%3;
                    nkg[d] = fmaf(C3[j][e],   dqg[c], nkg[d]);
                    nkh[d] = fmaf(C3[j][2+e], dqh[c], nkh[d]);
                }
            }
            #pragma unroll
            for (int d=0;d<8;++d){
                kbuf[(sg*16+d)*NTHR+tid]   = nkg[d];
                kbuf[(sg*16+8+d)*NTHR+tid] = nkh[d];
            }
        }

        // ---- z += sum_p B[p] k_p ----
        #pragma unroll
        for (int p=0;p<6;++p){
            const float c = cBt[p];
            #pragma unroll
            for (int d=0;d<8;++d){
                zg[d] = fmaf(c, kbuf[(p*16+d)*NTHR+tid],   zg[d]);
                zh[d] = fmaf(c, kbuf[(p*16+8+d)*NTHR+tid], zh[d]);
            }
        }
    }

    // ---- readout ----
    float pg = 0.f, ph = 0.f;
    #pragma unroll
    for (int d=0;d<8;++d){
        const float wv = w_ro[8*tg+d];
        pg = fmaf(zg[d], wv, pg);
        ph = fmaf(zh[d], wv, ph);
    }
    pg += __shfl_xor_sync(0xffffffffu, pg, 1);
    pg += __shfl_xor_sync(0xffffffffu, pg, 2);
    ph += __shfl_xor_sync(0xffffffffu, ph, 1);
    ph += __shfl_xor_sync(0xffffffffu, ph, 2);
    if (tg == 0){
        const float br = b_ro[0];
        if (rowg < Bn) out[rowg] = 1.0f/(1.0f + expf(-(pg + br)));
        if (rowh < Bn) out[rowh] = 1.0f/(1.0f + expf(-(ph + br)));
    }
}

extern "C" void kernel_launch(void* const* d_in, const int* in_sizes, int n_in,
                              void* d_out, int out_size)
{
    const float* times=(const float*)d_in[0];
    const float* grad =(const float*)d_in[1];
    const float* w1=(const float*)d_in[2];  const float* b1=(const float*)d_in[3];
    const float* w2=(const float*)d_in[4];  const float* b2=(const float*)d_in[5];
    const float* w3=(const float*)d_in[6];  const float* b3=(const float*)d_in[7];
    const float* we=(const float*)d_in[8];  const float* be=(const float*)d_in[9];
    const float* wr=(const float*)d_in[10]; const float* br=(const float*)d_in[11];
    float* out=(float*)d_out;

    const int Bn = in_sizes[1] / (Tt*3);
    const int nblocks = (Bn + MROWS - 1) / MROWS;

    cudaFuncSetAttribute(ncde_mma, cudaFuncAttributeMaxDynamicSharedMemorySize,
                         (int)SMEM_BYTES);
    ncde_mma<<<nblocks, NTHR, SMEM_BYTES>>>(
        times, grad, w1, b1, w2, b2, w3, b3, we, be, wr, br, out, Bn);
}

// round 8
// speedup vs baseline: 1.0490x; 1.0490x over previous
#include <cuda_runtime.h>
#include <cuda_fp16.h>
#include <math.h>

typedef unsigned int u32;

#define NSTEPS 511
#define Tt     512
#define NTHR   256
#define MROWS  128

// ---- smem byte offsets ----
#define SM_W1 0            // 16 tiles * 512B
#define SM_W2 8192         // 32 tiles
#define SM_W3 24576        // 48 tiles
#define SM_B1 49152        // f32[64]
#define SM_B2 49408        // f32[64]
#define SM_B3 49664        // f32[96] (permuted)
#define SM_KST 50048       // f32[6][16][NTHR]
#define SMEM_BYTES (SM_KST + 6*16*NTHR*4)   // 148,352 B

__constant__ float cA6[6][5] = {
    {0.f,0.f,0.f,0.f,0.f},
    {0.161f,0.f,0.f,0.f,0.f},
    {-0.008480655492356989f,0.335480655492357f,0.f,0.f,0.f},
    {2.8971530571054935f,-6.359448489975075f,4.3622954328695815f,0.f,0.f},
    {5.325864828439257f,-11.748883564062828f,7.4955393428898365f,-0.09249506636175525f,0.f},
    {5.86145544294642f,-12.92096931784711f,8.159367898576159f,-0.071584973281401f,-0.028269050394068383f}};
__constant__ float cBt[6] = {
    0.09646076681806523f,0.01f,0.4798896504144996f,
    1.379008574103742f,-3.290069515436081f,2.324710524099774f};

// fast tanh: 1 - 2/(2^(x*2/ln2)+1). MUFU.EX2 + MUFU.RCP, ~1e-6 rel err,
// exact saturation at +-1. 5 instructions.
__device__ __forceinline__ float ftanh(float x){
    float r;
    asm("{\n\t.reg .f32 e;\n\t"
        "mul.f32 e, %1, 0f4038AA3B;\n\t"      // x * 2.885390082 (= 2/ln2)
        "ex2.approx.f32 e, e;\n\t"
        "add.f32 e, e, 0f3F800000;\n\t"       // + 1.0
        "rcp.approx.f32 e, e;\n\t"
        "fma.rn.f32 %0, e, 0fC0000000, 0f3F800000;\n\t"  // 1 - 2r
        "}" : "=f"(r) : "f"(x));
    return r;
}

// physical A-col p (0..31) -> logical h index
__device__ __forceinline__ int hphys(int p){
    return 8*((p&7)>>1) + 2*(p>>3) + (p&1);
}
// physical L3 out col p3 (0..95) -> logical w3 row (3h+c)
__device__ __forceinline__ int w3row(int p3){
    int j = p3>>3, r = p3&7, tg = r>>1, e = r&1;
    int q = 2*j + e, d = q/3, c = q%3;
    return 3*(8*tg + d) + c;
}

__device__ __forceinline__ u32 h2p(float x, float y){
    return (u32)__half_as_ushort(__float2half_rn(x))
         | ((u32)__half_as_ushort(__float2half_rn(y)) << 16);
}
__device__ __forceinline__ void split2(float x, float y, u32& hi, u32& lo){
    __half hx = __float2half_rn(x), hy = __float2half_rn(y);
    hi = (u32)__half_as_ushort(hx) | ((u32)__half_as_ushort(hy) << 16);
    lo = h2p(x - __half2float(hx), y - __half2float(hy));
}

__device__ __forceinline__ void mma16816(float* c, const u32* a, u32 b0, u32 b1){
    asm("mma.sync.aligned.m16n8k16.row.col.f32.f16.f16.f32 "
        "{%0,%1,%2,%3}, {%4,%5,%6,%7}, {%8,%9}, {%0,%1,%2,%3};"
        : "+f"(c[0]), "+f"(c[1]), "+f"(c[2]), "+f"(c[3])
        : "r"(a[0]), "r"(a[1]), "r"(a[2]), "r"(a[3]), "r"(b0), "r"(b1));
}

template<int NJ, int NT>
__device__ __forceinline__ void runLayer(const u32* __restrict__ tiles,
                                         const float* __restrict__ bias,
                                         const u32 (*ah)[4], const u32 (*al)[4],
                                         float (*C)[4], int lane, int tg)
{
    #pragma unroll
    for (int j=0;j<NJ;++j){
        float2 bb = *(const float2*)(bias + 8*j + 2*tg);
        C[j][0]=bb.x; C[j][1]=bb.y; C[j][2]=bb.x; C[j][3]=bb.y;
    }
    #pragma unroll
    for (int t=0;t<NT;++t){
        uint4 w[NJ];
        #pragma unroll
        for (int j=0;j<NJ;++j)
            w[j] = *(const uint4*)(tiles + (j*NT+t)*128 + lane*4);
        #pragma unroll
        for (int j=0;j<NJ;++j) mma16816(C[j], ah[t], w[j].x, w[j].y);  // Ah*Bh
        #pragma unroll
        for (int j=0;j<NJ;++j) mma16816(C[j], al[t], w[j].x, w[j].y);  // Al*Bh
        #pragma unroll
        for (int j=0;j<NJ;++j) mma16816(C[j], ah[t], w[j].z, w[j].w);  // Ah*Bl
    }
}

// tanh + hi/lo split: C n-tile pair (2t,2t+1) -> A k-tile t
template<int NTo>
__device__ __forceinline__ void actSplit(const float (*C)[4], u32 (*ah)[4], u32 (*al)[4]){
    #pragma unroll
    for (int t=0;t<NTo;++t){
        split2(ftanh(C[2*t][0]),   ftanh(C[2*t][1]),   ah[t][0], al[t][0]);
        split2(ftanh(C[2*t][2]),   ftanh(C[2*t][3]),   ah[t][1], al[t][1]);
        split2(ftanh(C[2*t+1][0]), ftanh(C[2*t+1][1]), ah[t][2], al[t][2]);
        split2(ftanh(C[2*t+1][2]), ftanh(C[2*t+1][3]), ah[t][3], al[t][3]);
    }
}

__global__ void __launch_bounds__(NTHR, 1)
ncde_mma(const float* __restrict__ times, const float* __restrict__ grad,
         const float* __restrict__ w1, const float* __restrict__ pb1,
         const float* __restrict__ w2, const float* __restrict__ pb2,
         const float* __restrict__ w3, const float* __restrict__ pb3,
         const float* __restrict__ w_enc, const float* __restrict__ b_enc,
         const float* __restrict__ w_ro, const float* __restrict__ b_ro,
         float* __restrict__ out, int Bn)
{
    extern __shared__ float sm[];
    char* smc = (char*)sm;
    u32* tw1 = (u32*)(smc + SM_W1);
    u32* tw2 = (u32*)(smc + SM_W2);
    u32* tw3 = (u32*)(smc + SM_W3);
    float* b1s = (float*)(smc + SM_B1);
    float* b2s = (float*)(smc + SM_B2);
    float* b3s = (float*)(smc + SM_B3);
    float* kbuf = (float*)(smc + SM_KST);

    const int tid = threadIdx.x, warp = tid>>5, lane = tid&31;
    const int g = lane>>2, tg = lane&3;

    // ---- build weight fragment tiles (hi/lo f16) ----
    for (int s = tid; s < 16*32; s += NTHR){
        int tile = s>>5, l = s&31;
        int j = tile>>1, t = tile&1;
        int gg = l>>2, tt = l&3;
        int n = 8*j+gg, k0 = 16*t+2*tt;
        float f0 = w1[n*32 + hphys(k0)],   f1 = w1[n*32 + hphys(k0+1)];
        float f8 = w1[n*32 + hphys(k0+8)], f9 = w1[n*32 + hphys(k0+9)];
        u32 h01,l01,h89,l89;
        split2(f0,f1,h01,l01); split2(f8,f9,h89,l89);
        u32* d = tw1 + tile*128 + l*4;
        d[0]=h01; d[1]=h89; d[2]=l01; d[3]=l89;
    }
    for (int s = tid; s < 32*32; s += NTHR){
        int tile = s>>5, l = s&31;
        int j = tile>>2, t = tile&3;
        int gg = l>>2, tt = l&3;
        int n = 8*j+gg, k0 = 16*t+2*tt;
        float f0 = w2[n*64+k0],   f1 = w2[n*64+k0+1];
        float f8 = w2[n*64+k0+8], f9 = w2[n*64+k0+9];
        u32 h01,l01,h89,l89;
        split2(f0,f1,h01,l01); split2(f8,f9,h89,l89);
        u32* d = tw2 + tile*128 + l*4;
        d[0]=h01; d[1]=h89; d[2]=l01; d[3]=l89;
    }
    for (int s = tid; s < 48*32; s += NTHR){
        int tile = s>>5, l = s&31;
        int j = tile>>2, t = tile&3;
        int gg = l>>2, tt = l&3;
        int n = 8*j+gg, k0 = 16*t+2*tt;
        int rr = w3row(n);
        float f0 = w3[rr*64+k0],   f1 = w3[rr*64+k0+1];
        float f8 = w3[rr*64+k0+8], f9 = w3[rr*64+k0+9];
        u32 h01,l01,h89,l89;
        split2(f0,f1,h01,l01); split2(f8,f9,h89,l89);
        u32* d = tw3 + tile*128 + l*4;
        d[0]=h01; d[1]=h89; d[2]=l01; d[3]=l89;
    }
    if (tid < 64) b1s[tid] = pb1[tid];
    if (tid < 64) b2s[tid] = pb2[tid];
    if (tid < 96) b3s[tid] = pb3[w3row(tid)];
    __syncthreads();

    // ---- per-thread state: rows g and g+8 of warp's 16-row block ----
    const int base = blockIdx.x*MROWS + warp*16;
    const int rowg = base + g, rowh = rowg + 8;
    const int rgc = (rowg < Bn) ? rowg : (Bn-1);
    const int rhc = (rowh < Bn) ? rowh : (Bn-1);
    const float dt = times[1] - times[0];
    const float* gA = grad + (size_t)rgc * (Tt*3);
    const float* gB = grad + (size_t)rhc * (Tt*3);

    float zg[8], zh[8];
    #pragma unroll
    for (int d=0; d<8; ++d){
        float v = w_enc[8*tg+d] + b_enc[8*tg+d];
        zg[d] = v; zh[d] = v;
    }

    #pragma unroll 1
    for (int n=0; n<NSTEPS; ++n){
        float dqg[3], dqh[3];
        #pragma unroll
        for (int c=0;c<3;++c){ dqg[c] = gA[n*3+c]*dt; dqh[c] = gB[n*3+c]*dt; }

        #pragma unroll 1
        for (int sg=0; sg<6; ++sg){
            // ---- stage combine: Y = z + sum_p A[sg][p] k_p ----
            float Yg[8], Yh[8];
            #pragma unroll
            for (int d=0;d<8;++d){ Yg[d]=zg[d]; Yh[d]=zh[d]; }
            for (int p=0;p<sg;++p){
                const float c = cA6[sg][p];
                #pragma unroll
                for (int d=0;d<8;++d){
                    Yg[d] = fmaf(c, kbuf[(p*16+d)*NTHR+tid],   Yg[d]);
                    Yh[d] = fmaf(c, kbuf[(p*16+8+d)*NTHR+tid], Yh[d]);
                }
            }
            u32 yah[2][4], yal[2][4];
            #pragma unroll
            for (int t=0;t<2;++t){
                split2(Yg[4*t],   Yg[4*t+1], yah[t][0], yal[t][0]);
                split2(Yh[4*t],   Yh[4*t+1], yah[t][1], yal[t][1]);
                split2(Yg[4*t+2], Yg[4*t+3], yah[t][2], yal[t][2]);
                split2(Yh[4*t+2], Yh[4*t+3], yah[t][3], yal[t][3]);
            }

            // ---- L1 ----
            float C1[8][4];
            runLayer<8,2>(tw1, b1s, yah, yal, C1, lane, tg);
            u32 a2h[4][4], a2l[4][4];
            actSplit<4>(C1, a2h, a2l);

            // ---- L2 ----
            float C2[8][4];
            runLayer<8,4>(tw2, b2s, a2h, a2l, C2, lane, tg);
            u32 a3h[4][4], a3l[4][4];
            actSplit<4>(C2, a3h, a3l);

            // ---- L3 ----
            float C3[12][4];
            runLayer<12,4>(tw3, b3s, a3h, a3l, C3, lane, tg);

            // ---- dq contraction -> k ----
            float nkg[8], nkh[8];
            #pragma unroll
            for (int d=0;d<8;++d){ nkg[d]=0.f; nkh[d]=0.f; }
            #pragma unroll
            for (int j=0;j<12;++j){
                #pragma unroll
                for (int e=0;e<2;++e){
                    const int q = 2*j+e, d = q/3, c = q%3;
                    nkg[d] = fmaf(C3[j][e],   dqg[c], nkg[d]);
                    nkh[d] = fmaf(C3[j][2+e], dqh[c], nkh[d]);
                }
            }
            #pragma unroll
            for (int d=0;d<8;++d){
                kbuf[(sg*16+d)*NTHR+tid]   = nkg[d];
                kbuf[(sg*16+8+d)*NTHR+tid] = nkh[d];
            }
        }

        // ---- z += sum_p B[p] k_p ----
        #pragma unroll
        for (int p=0;p<6;++p){
            const float c = cBt[p];
            #pragma unroll
            for (int d=0;d<8;++d){
                zg[d] = fmaf(c, kbuf[(p*16+d)*NTHR+tid],   zg[d]);
                zh[d] = fmaf(c, kbuf[(p*16+8+d)*NTHR+tid], zh[d]);
            }
        }
    }

    // ---- readout ----
    float pg = 0.f, ph = 0.f;
    #pragma unroll
    for (int d=0;d<8;++d){
        const float wv = w_ro[8*tg+d];
        pg = fmaf(zg[d], wv, pg);
        ph = fmaf(zh[d], wv, ph);
    }
    pg += __shfl_xor_sync(0xffffffffu, pg, 1);
    pg += __shfl_xor_sync(0xffffffffu, pg, 2);
    ph += __shfl_xor_sync(0xffffffffu, ph, 1);
    ph += __shfl_xor_sync(0xffffffffu, ph, 2);
    if (tg == 0){
        const float br = b_ro[0];
        if (rowg < Bn) out[rowg] = 1.0f/(1.0f + expf(-(pg + br)));
        if (rowh < Bn) out[rowh] = 1.0f/(1.0f + expf(-(ph + br)));
    }
}

extern "C" void kernel_launch(void* const* d_in, const int* in_sizes, int n_in,
                              void* d_out, int out_size)
{
    const float* times=(const float*)d_in[0];
    const float* grad =(const float*)d_in[1];
    const float* w1=(const float*)d_in[2];  const float* b1=(const float*)d_in[3];
    const float* w2=(const float*)d_in[4];  const float* b2=(const float*)d_in[5];
    const float* w3=(const float*)d_in[6];  const float* b3=(const float*)d_in[7];
    const float* we=(const float*)d_in[8];  const float* be=(const float*)d_in[9];
    const float* wr=(const float*)d_in[10]; const float* br=(const float*)d_in[11];
    float* out=(float*)d_out;

    const int Bn = in_sizes[1] / (Tt*3);
    const int nblocks = (Bn + MROWS - 1) / MROWS;

    cudaFuncSetAttribute(ncde_mma, cudaFuncAttributeMaxDynamicSharedMemorySize,
                         (int)SMEM_BYTES);
    ncde_mma<<<nblocks, NTHR, SMEM_BYTES>>>(
        times, grad, w1, b1, w2, b2, w3, b3, we, be, wr, br, out, Bn);
}